// round 1
// baseline (speedup 1.0000x reference)
#include <cuda_runtime.h>

#define CCH 64          // channels
#define CO 8            // q/k channels (C/8)
#define WIN 13          // window
#define WPB 8           // windows per block
#define TP 104          // voxels per tile = WPB*WIN
#define TPP 108         // padded row (bank-conflict-free, /4 for float4 stores)
#define NTHREADS 256
#define NVOX 53248      // D*H*W = 13*64*64
#define NB (NVOX / WIN) // 4096 windows per batch
#define TILES_PER_B (NB / WPB) // 512

struct Smem {
    float xs[CCH][TPP];         // raw x tile
    float ys[CCH][TPP];         // x @ att^T
    float q[CO][TPP];
    float k[CO][TPP];
    float att[WPB][WIN * WIN];
    float wq[CO][CCH];
    float wk[CO][CCH];
    float wv[CCH][CCH];
    float bq[CO];
    float bk[CO];
    float bv[CCH];
};

__global__ __launch_bounds__(NTHREADS, 2)
void win_attn_kernel(const float* __restrict__ x,
                     const float* __restrict__ wq, const float* __restrict__ bq,
                     const float* __restrict__ wk, const float* __restrict__ bk,
                     const float* __restrict__ wv, const float* __restrict__ bv,
                     float* __restrict__ out) {
    extern __shared__ char smem_raw[];
    Smem& s = *reinterpret_cast<Smem*>(smem_raw);

    const int tid  = threadIdx.x;
    const int b    = blockIdx.x / TILES_PER_B;
    const int tile = blockIdx.x % TILES_PER_B;
    const long n0  = (long)tile * TP;

    const float* xb = x   + (long)b * CCH * NVOX + n0;
    float*       ob = out + (long)b * CCH * NVOX + n0;

    // ---- load weights/biases into shared ----
    for (int i = tid; i < CO * CCH; i += NTHREADS) {
        s.wq[0][i] = wq[i];
        s.wk[0][i] = wk[i];
    }
    for (int i = tid; i < CCH * CCH; i += NTHREADS)
        s.wv[0][i] = wv[i];
    if (tid < CO)  { s.bq[tid] = bq[tid]; s.bk[tid] = bk[tid]; }
    if (tid < CCH) s.bv[tid] = bv[tid];

    // ---- load x tile: 64 rows x 104 floats, vec4 coalesced ----
    for (int i = tid; i < CCH * (TP / 4); i += NTHREADS) {
        int r  = i / (TP / 4);
        int c4 = i % (TP / 4);
        float4 v = *reinterpret_cast<const float4*>(xb + (long)r * NVOX + c4 * 4);
        s.xs[r][c4 * 4 + 0] = v.x;
        s.xs[r][c4 * 4 + 1] = v.y;
        s.xs[r][c4 * 4 + 2] = v.z;
        s.xs[r][c4 * 4 + 3] = v.w;
    }
    __syncthreads();

    // ---- q / k projections: 8 x 104 each ----
    for (int i = tid; i < CO * TP; i += NTHREADS) {
        int o = i / TP, p = i % TP;
        float aq = s.bq[o], ak = s.bk[o];
#pragma unroll
        for (int c = 0; c < CCH; c++) {
            float xv = s.xs[c][p];
            aq = fmaf(s.wq[o][c], xv, aq);
            ak = fmaf(s.wk[o][c], xv, ak);
        }
        s.q[o][p] = aq;
        s.k[o][p] = ak;
    }
    __syncthreads();

    // ---- scores: per window 13x13 over 8 q/k channels ----
    for (int i = tid; i < WPB * WIN * WIN; i += NTHREADS) {
        int w  = i / (WIN * WIN);
        int ij = i % (WIN * WIN);
        int ii = ij / WIN, jj = ij % WIN;
        float acc = 0.f;
#pragma unroll
        for (int o = 0; o < CO; o++)
            acc = fmaf(s.q[o][w * WIN + ii], s.k[o][w * WIN + jj], acc);
        s.att[w][ij] = acc;
    }
    __syncthreads();

    // ---- softmax over each of the 104 rows (length 13) ----
    for (int i = tid; i < TP; i += NTHREADS) {
        int w = i / WIN, ii = i % WIN;
        float* row = &s.att[w][ii * WIN];
        float m = row[0];
#pragma unroll
        for (int j = 1; j < WIN; j++) m = fmaxf(m, row[j]);
        float sum = 0.f;
#pragma unroll
        for (int j = 0; j < WIN; j++) {
            float e = __expf(row[j] - m);
            row[j] = e;
            sum += e;
        }
        float inv = __frcp_rn(sum);
#pragma unroll
        for (int j = 0; j < WIN; j++) row[j] *= inv;
    }
    __syncthreads();

    // ---- y = x . att^T  (apply attention to raw channels; valid since
    //      softmax rows sum to 1, so wv/bv commute through) ----
    for (int i = tid; i < CCH * TP; i += NTHREADS) {
        int c = i / TP, p = i % TP;
        int w = p / WIN, ii = p % WIN;
        const float* xr = &s.xs[c][w * WIN];
        const float* ar = &s.att[w][ii * WIN];
        float acc = 0.f;
#pragma unroll
        for (int j = 0; j < WIN; j++) acc = fmaf(xr[j], ar[j], acc);
        s.ys[c][p] = acc;
    }
    __syncthreads();

    // ---- out = wv @ y + bv, register tile: 2 channels x 13 positions ----
    const int ct = tid >> 3;          // 0..31
    const int pt = tid & 7;           // 0..7
    const int c0 = ct * 2;
    const int p0 = pt * WIN;

    float acc0[WIN], acc1[WIN];
    const float bv0 = s.bv[c0], bv1 = s.bv[c0 + 1];
#pragma unroll
    for (int j = 0; j < WIN; j++) { acc0[j] = bv0; acc1[j] = bv1; }

#pragma unroll 4
    for (int cc = 0; cc < CCH; cc++) {
        float w0 = s.wv[c0][cc];
        float w1 = s.wv[c0 + 1][cc];
        const float* yr = &s.ys[cc][p0];
#pragma unroll
        for (int j = 0; j < WIN; j++) {
            float yv = yr[j];
            acc0[j] = fmaf(w0, yv, acc0[j]);
            acc1[j] = fmaf(w1, yv, acc1[j]);
        }
    }

    float* o0 = ob + (long)c0 * NVOX + p0;
    float* o1 = o0 + NVOX;
#pragma unroll
    for (int j = 0; j < WIN; j++) { o0[j] = acc0[j]; o1[j] = acc1[j]; }
}

extern "C" void kernel_launch(void* const* d_in, const int* in_sizes, int n_in,
                              void* d_out, int out_size) {
    const float* x  = (const float*)d_in[0];
    const float* wq = (const float*)d_in[1];
    const float* bq = (const float*)d_in[2];
    const float* wk = (const float*)d_in[3];
    const float* bk = (const float*)d_in[4];
    const float* wv = (const float*)d_in[5];
    const float* bv = (const float*)d_in[6];
    float* out = (float*)d_out;

    const int B = in_sizes[0] / (CCH * NVOX);   // 8
    const int smem = (int)sizeof(Smem);

    static bool attr_set = false;
    if (!attr_set) {
        cudaFuncSetAttribute(win_attn_kernel,
                             cudaFuncAttributeMaxDynamicSharedMemorySize, smem);
        attr_set = true;
    }

    dim3 grid(B * TILES_PER_B);
    win_attn_kernel<<<grid, NTHREADS, smem>>>(x, wq, bq, wk, bk, wv, bv, out);
}